// round 11
// baseline (speedup 1.0000x reference)
#include <cuda_runtime.h>
#include <math_constants.h>

// Problem constants (fixed: centers [8, 4096, 3] fp32)
#define BATCH    8
#define NPTS     4096
#define TOTPTS   (BATCH * NPTS)       // 32768
#define TPB      128                  // threads per block
#define IPT      4                    // i-points per thread
#define ITILE    (TPB * IPT)          // 512 i per block
#define NITILES  (NPTS / ITILE)       // 8
#define SSPLIT   64                   // j-splits
#define JT       (NPTS / SSPLIT)      // 64 j per block
#define NBLK_MIN (BATCH * NITILES * SSPLIT)   // 4096
#define TARGET_F 0.2f

// Scratch (static device globals — no allocation allowed).
// g_key[point]: order-reversed monotone float key. key==0 decodes to the
// "+inf" sentinel, so the zero-initialized state IS the initialized state;
// the fused tail resets keys to 0 after reading (graph-replay-safe).
__device__ unsigned int g_key[TOTPTS];    // 128 KB, L2-resident
__device__ unsigned int g_sync;           // zero-init; self-resets

// ---- order-reversed monotone float<->key (min via RED.MAX) ----
__device__ __forceinline__ unsigned int f2key(float f) {
    unsigned int b = __float_as_uint(f);
    unsigned int mono = (b & 0x80000000u) ? ~b : (b | 0x80000000u);
    return ~mono;   // larger float -> smaller key; atomicMax keeps the min
}
__device__ __forceinline__ float key2f(unsigned int k) {
    unsigned int mono = ~k;
    unsigned int b = (mono & 0x80000000u) ? (mono ^ 0x80000000u) : ~mono;
    return __uint_as_float(b);
}

// ---- packed f32x2 helpers (FFMA2: only reachable via PTX) ----
__device__ __forceinline__ unsigned long long pack2(float a, float b) {
    unsigned long long r;
    asm("mov.b64 %0, {%1, %2};" : "=l"(r) : "f"(a), "f"(b));
    return r;
}
__device__ __forceinline__ unsigned long long fma2(unsigned long long a,
                                                   unsigned long long b,
                                                   unsigned long long c) {
    unsigned long long d;
    asm("fma.rn.f32x2 %0, %1, %2, %3;" : "=l"(d) : "l"(a), "l"(b), "l"(c));
    return d;
}
__device__ __forceinline__ float2 unpack2(unsigned long long v) {
    float2 f;
    asm("mov.b64 {%0, %1}, %2;" : "=f"(f.x), "=f"(f.y) : "l"(v));
    return f;
}

__global__ void __launch_bounds__(TPB)
nn_fused_kernel(const float* __restrict__ centers, float* __restrict__ out)
{
    // SoA j-tile: LDS.128 per array yields pre-packed {j,j+1} f32x2 lanes
    __shared__ __align__(16) float spx[JT], spy[JT], spz[JT], spw[JT];
    __shared__ float red[TPB];
    __shared__ bool  is_last;

    const int blk = blockIdx.x;
    const int s   = blk & (SSPLIT - 1);            // j-split
    const int it  = (blk >> 6) & (NITILES - 1);    // i-tile
    const int b   = blk >> 9;                      // batch
    const int tid = threadIdx.x;

    const float* cb = centers + (size_t)b * NPTS * 3;
    const int j_lo  = s  * JT;
    const int i_lo  = it * ITILE;

    // Stage j-tile (64 points)
    for (int p = tid; p < JT; p += TPB) {
        float x = cb[3 * (j_lo + p) + 0];
        float y = cb[3 * (j_lo + p) + 1];
        float z = cb[3 * (j_lo + p) + 2];
        spx[p] = x; spy[p] = y; spz[p] = z;
        spw[p] = fmaf(x, x, fmaf(y, y, z * z));
    }

    // i-constants, pre-packed {c,c} once
    unsigned long long ax2[IPT], ay2[IPT], az2[IPT];
    float sqi[IPT], tminA[IPT], tminB[IPT];
    int   msel[IPT];   // local j index equal to this i (may be out of range)
    #pragma unroll
    for (int k = 0; k < IPT; ++k) {
        const int gi = i_lo + tid + k * TPB;
        float x = cb[3 * gi + 0];
        float y = cb[3 * gi + 1];
        float z = cb[3 * gi + 2];
        ax2[k] = pack2(-2.0f * x, -2.0f * x);
        ay2[k] = pack2(-2.0f * y, -2.0f * y);
        az2[k] = pack2(-2.0f * z, -2.0f * z);
        sqi[k] = fmaf(x, x, fmaf(y, y, z * z));
        tminA[k] = CUDART_INF_F;
        tminB[k] = CUDART_INF_F;
        msel[k] = gi - j_lo;
    }
    __syncthreads();

    const ulonglong2* px2 = (const ulonglong2*)spx;
    const ulonglong2* py2 = (const ulonglong2*)spy;
    const ulonglong2* pz2 = (const ulonglong2*)spz;
    const ulonglong2* pw2 = (const ulonglong2*)spw;

    if ((s >> 3) != it) {
        // Off-diagonal block: clean fully-unrolled loop, no compares
        #pragma unroll
        for (int q = 0; q < JT / 4; ++q) {
            const ulonglong2 px = px2[q], py = py2[q], pz = pz2[q], pw = pw2[q];
            #pragma unroll
            for (int k = 0; k < IPT; ++k) {
                unsigned long long t0 = fma2(pz.x, az2[k], pw.x);
                t0 = fma2(py.x, ay2[k], t0);
                t0 = fma2(px.x, ax2[k], t0);
                unsigned long long t1 = fma2(pz.y, az2[k], pw.y);
                t1 = fma2(py.y, ay2[k], t1);
                t1 = fma2(px.y, ax2[k], t1);
                float2 a = unpack2(t0), c = unpack2(t1);
                tminA[k] = fminf(tminA[k], fminf(a.x, a.y));
                tminB[k] = fminf(tminB[k], fminf(c.x, c.y));
            }
        }
    } else {
        // Diagonal block (1/8 of blocks): predicate out j == i
        #pragma unroll
        for (int q = 0; q < JT / 4; ++q) {
            const int jb = q * 4;
            const ulonglong2 px = px2[q], py = py2[q], pz = pz2[q], pw = pw2[q];
            #pragma unroll
            for (int k = 0; k < IPT; ++k) {
                unsigned long long t0 = fma2(pz.x, az2[k], pw.x);
                t0 = fma2(py.x, ay2[k], t0);
                t0 = fma2(px.x, ax2[k], t0);
                unsigned long long t1 = fma2(pz.y, az2[k], pw.y);
                t1 = fma2(py.y, ay2[k], t1);
                t1 = fma2(px.y, ax2[k], t1);
                float2 a = unpack2(t0), c = unpack2(t1);
                const int m = msel[k];
                a.x = (jb + 0 == m) ? CUDART_INF_F : a.x;
                a.y = (jb + 1 == m) ? CUDART_INF_F : a.y;
                c.x = (jb + 2 == m) ? CUDART_INF_F : c.x;
                c.y = (jb + 3 == m) ? CUDART_INF_F : c.y;
                tminA[k] = fminf(tminA[k], fminf(a.x, a.y));
                tminB[k] = fminf(tminB[k], fminf(c.x, c.y));
            }
        }
    }

    // Split-reduction via RED.MAX on order-reversed keys (== float min).
    // min is associative/commutative -> bit-exact in any arrival order.
    unsigned int* gk = g_key + b * NPTS + i_lo + tid;
    #pragma unroll
    for (int k = 0; k < IPT; ++k)
        atomicMax(&gk[k * TPB], f2key(sqi[k] + fminf(tminA[k], tminB[k])));

    // ---- fused final: last block computes the loss (no second launch) ----
    __threadfence();                   // publish RED.MAX results
    if (tid == 0)
        is_last = (atomicAdd(&g_sync, 1u) == NBLK_MIN - 1);
    __syncthreads();
    if (!is_last) return;

    __threadfence();                   // acquire all blocks' key writes

    // 256 points per thread: independent loads (MLP-deep), fixed-order sum.
    float acc = 0.0f;
    #pragma unroll 8
    for (int pt = tid; pt < TOTPTS; pt += TPB) {
        float m = key2f(g_key[pt]);
        g_key[pt] = 0u;                              // reset for next replay
        float diff = sqrtf(fmaxf(m, 0.0f)) - TARGET_F;  // clamp like reference
        acc = fmaf(diff, diff, acc);
    }
    red[tid] = acc;
    __syncthreads();
    #pragma unroll
    for (int st = TPB / 2; st > 0; st >>= 1) {
        if (tid < st) red[tid] += red[tid + st];
        __syncthreads();
    }
    if (tid == 0) {
        out[0] = red[0] * (1.0f / (float)TOTPTS);
        g_sync = 0;                                  // reset for next replay
    }
}

extern "C" void kernel_launch(void* const* d_in, const int* in_sizes, int n_in,
                              void* d_out, int out_size)
{
    const float* centers = (const float*)d_in[0];
    float* out = (float*)d_out;

    nn_fused_kernel<<<NBLK_MIN, TPB>>>(centers, out);
}

// round 12
// speedup vs baseline: 1.0047x; 1.0047x over previous
#include <cuda_runtime.h>
#include <math_constants.h>

// Problem constants (fixed: centers [8, 4096, 3] fp32)
#define BATCH    8
#define NPTS     4096
#define TOTPTS   (BATCH * NPTS)       // 32768
#define TPB      128                  // threads per block
#define IPT      4                    // i-points per thread
#define ITILE    (TPB * IPT)          // 512 i per block
#define NITILES  (NPTS / ITILE)       // 8
#define SSPLIT   64                   // j-splits
#define JT       (NPTS / SSPLIT)      // 64 j per block
#define NBLK_MIN (BATCH * NITILES * SSPLIT)   // 4096
#define TARGET_F 0.2f

// Scratch (static device globals — no allocation allowed).
// g_key[point]: order-reversed monotone float key. key==0 decodes to the
// "+inf" sentinel, so the zero-initialized state IS the initialized state;
// the fused tail resets keys to 0 after reading (graph-replay-safe).
__device__ unsigned int g_key[TOTPTS];    // 128 KB, L2-resident
__device__ unsigned int g_sync;           // zero-init; self-resets

// ---- order-reversed monotone float<->key (min via RED.MAX) ----
__device__ __forceinline__ unsigned int f2key(float f) {
    unsigned int b = __float_as_uint(f);
    unsigned int mono = (b & 0x80000000u) ? ~b : (b | 0x80000000u);
    return ~mono;   // larger float -> smaller key; atomicMax keeps the min
}
__device__ __forceinline__ float key2f(unsigned int k) {
    unsigned int mono = ~k;
    unsigned int b = (mono & 0x80000000u) ? (mono ^ 0x80000000u) : ~mono;
    return __uint_as_float(b);
}

// GPU-scope acq_rel fetch-add: replaces __threadfence() entirely.
// Release publishes this block's prior RED.MAX ops; acquire (in whichever
// block turns out to be last) pulls in every other block's REDs.
__device__ __forceinline__ unsigned int atom_add_acq_rel(unsigned int* p,
                                                         unsigned int v) {
    unsigned int old;
    asm volatile("atom.acq_rel.gpu.global.add.u32 %0, [%1], %2;"
                 : "=r"(old) : "l"(p), "r"(v) : "memory");
    return old;
}

// ---- packed f32x2 helpers (FFMA2: only reachable via PTX) ----
__device__ __forceinline__ unsigned long long pack2(float a, float b) {
    unsigned long long r;
    asm("mov.b64 %0, {%1, %2};" : "=l"(r) : "f"(a), "f"(b));
    return r;
}
__device__ __forceinline__ unsigned long long fma2(unsigned long long a,
                                                   unsigned long long b,
                                                   unsigned long long c) {
    unsigned long long d;
    asm("fma.rn.f32x2 %0, %1, %2, %3;" : "=l"(d) : "l"(a), "l"(b), "l"(c));
    return d;
}
__device__ __forceinline__ float2 unpack2(unsigned long long v) {
    float2 f;
    asm("mov.b64 {%0, %1}, %2;" : "=f"(f.x), "=f"(f.y) : "l"(v));
    return f;
}

__global__ void __launch_bounds__(TPB)
nn_fused_kernel(const float* __restrict__ centers, float* __restrict__ out)
{
    // SoA j-tile: LDS.128 per array yields pre-packed {j,j+1} f32x2 lanes
    __shared__ __align__(16) float spx[JT], spy[JT], spz[JT], spw[JT];
    __shared__ float red[TPB];
    __shared__ bool  is_last;

    const int blk = blockIdx.x;
    const int s   = blk & (SSPLIT - 1);            // j-split
    const int it  = (blk >> 6) & (NITILES - 1);    // i-tile
    const int b   = blk >> 9;                      // batch
    const int tid = threadIdx.x;

    const float* cb = centers + (size_t)b * NPTS * 3;
    const int j_lo  = s  * JT;
    const int i_lo  = it * ITILE;

    // Stage j-tile (64 points)
    for (int p = tid; p < JT; p += TPB) {
        float x = cb[3 * (j_lo + p) + 0];
        float y = cb[3 * (j_lo + p) + 1];
        float z = cb[3 * (j_lo + p) + 2];
        spx[p] = x; spy[p] = y; spz[p] = z;
        spw[p] = fmaf(x, x, fmaf(y, y, z * z));
    }

    // i-constants, pre-packed {c,c} once
    unsigned long long ax2[IPT], ay2[IPT], az2[IPT];
    float sqi[IPT], tminA[IPT], tminB[IPT];
    int   msel[IPT];   // local j index equal to this i (may be out of range)
    #pragma unroll
    for (int k = 0; k < IPT; ++k) {
        const int gi = i_lo + tid + k * TPB;
        float x = cb[3 * gi + 0];
        float y = cb[3 * gi + 1];
        float z = cb[3 * gi + 2];
        ax2[k] = pack2(-2.0f * x, -2.0f * x);
        ay2[k] = pack2(-2.0f * y, -2.0f * y);
        az2[k] = pack2(-2.0f * z, -2.0f * z);
        sqi[k] = fmaf(x, x, fmaf(y, y, z * z));
        tminA[k] = CUDART_INF_F;
        tminB[k] = CUDART_INF_F;
        msel[k] = gi - j_lo;
    }
    __syncthreads();

    const ulonglong2* px2 = (const ulonglong2*)spx;
    const ulonglong2* py2 = (const ulonglong2*)spy;
    const ulonglong2* pz2 = (const ulonglong2*)spz;
    const ulonglong2* pw2 = (const ulonglong2*)spw;

    if ((s >> 3) != it) {
        // Off-diagonal block: clean fully-unrolled loop, no compares
        #pragma unroll
        for (int q = 0; q < JT / 4; ++q) {
            const ulonglong2 px = px2[q], py = py2[q], pz = pz2[q], pw = pw2[q];
            #pragma unroll
            for (int k = 0; k < IPT; ++k) {
                unsigned long long t0 = fma2(pz.x, az2[k], pw.x);
                t0 = fma2(py.x, ay2[k], t0);
                t0 = fma2(px.x, ax2[k], t0);
                unsigned long long t1 = fma2(pz.y, az2[k], pw.y);
                t1 = fma2(py.y, ay2[k], t1);
                t1 = fma2(px.y, ax2[k], t1);
                float2 a = unpack2(t0), c = unpack2(t1);
                tminA[k] = fminf(tminA[k], fminf(a.x, a.y));
                tminB[k] = fminf(tminB[k], fminf(c.x, c.y));
            }
        }
    } else {
        // Diagonal block (1/8 of blocks): predicate out j == i
        #pragma unroll
        for (int q = 0; q < JT / 4; ++q) {
            const int jb = q * 4;
            const ulonglong2 px = px2[q], py = py2[q], pz = pz2[q], pw = pw2[q];
            #pragma unroll
            for (int k = 0; k < IPT; ++k) {
                unsigned long long t0 = fma2(pz.x, az2[k], pw.x);
                t0 = fma2(py.x, ay2[k], t0);
                t0 = fma2(px.x, ax2[k], t0);
                unsigned long long t1 = fma2(pz.y, az2[k], pw.y);
                t1 = fma2(py.y, ay2[k], t1);
                t1 = fma2(px.y, ax2[k], t1);
                float2 a = unpack2(t0), c = unpack2(t1);
                const int m = msel[k];
                a.x = (jb + 0 == m) ? CUDART_INF_F : a.x;
                a.y = (jb + 1 == m) ? CUDART_INF_F : a.y;
                c.x = (jb + 2 == m) ? CUDART_INF_F : c.x;
                c.y = (jb + 3 == m) ? CUDART_INF_F : c.y;
                tminA[k] = fminf(tminA[k], fminf(a.x, a.y));
                tminB[k] = fminf(tminB[k], fminf(c.x, c.y));
            }
        }
    }

    // Split-reduction via RED.MAX on order-reversed keys (== float min).
    // min is associative/commutative -> bit-exact in any arrival order.
    unsigned int* gk = g_key + b * NPTS + i_lo + tid;
    #pragma unroll
    for (int k = 0; k < IPT; ++k)
        atomicMax(&gk[k * TPB], f2key(sqi[k] + fminf(tminA[k], tminB[k])));

    // ---- fused final: last block computes the loss (no second launch) ----
    // NO MEMBAR: block sync + one acq_rel atom per block carries the ordering.
    __syncthreads();   // make all warps' REDs cumulative through tid 0
    if (tid == 0)
        is_last = (atom_add_acq_rel(&g_sync, 1u) == NBLK_MIN - 1);
    __syncthreads();   // propagate tid 0's acquire to the whole block
    if (!is_last) return;

    // 256 points per thread: independent loads (MLP-deep), fixed-order sum.
    float acc = 0.0f;
    #pragma unroll 8
    for (int pt = tid; pt < TOTPTS; pt += TPB) {
        float m = key2f(g_key[pt]);
        g_key[pt] = 0u;                              // reset for next replay
        float diff = sqrtf(fmaxf(m, 0.0f)) - TARGET_F;  // clamp like reference
        acc = fmaf(diff, diff, acc);
    }
    red[tid] = acc;
    __syncthreads();
    #pragma unroll
    for (int st = TPB / 2; st > 0; st >>= 1) {
        if (tid < st) red[tid] += red[tid + st];
        __syncthreads();
    }
    if (tid == 0) {
        out[0] = red[0] * (1.0f / (float)TOTPTS);
        g_sync = 0;                                  // reset for next replay
    }
}

extern "C" void kernel_launch(void* const* d_in, const int* in_sizes, int n_in,
                              void* d_out, int out_size)
{
    const float* centers = (const float*)d_in[0];
    float* out = (float*)d_out;

    nn_fused_kernel<<<NBLK_MIN, TPB>>>(centers, out);
}

// round 13
// speedup vs baseline: 1.7937x; 1.7854x over previous
#include <cuda_runtime.h>
#include <math_constants.h>

// Problem constants (fixed: centers [8, 4096, 3] fp32)
#define BATCH    8
#define NPTS     4096
#define TOTPTS   (BATCH * NPTS)     // 32768
#define TPB      128                // 4 warps
#define IPB      32                 // i-points per block (lane <-> i)
#define NBLK     (TOTPTS / IPB)     // 1024 blocks = one full wave
#define TILE     512                // j-tile in smem
#define NTILES   (NPTS / TILE)      // 8
#define QPW      32                 // quads (4 j) per warp per tile
#define PPT      (TILE / TPB)       // 4 staged points per thread
#define FIN_TPB  256
#define TARGET_F 0.2f

// Block partial losses: plain stores, no atomics anywhere.
__device__ float g_partials[NBLK];

// ---- packed f32x2 helpers (FFMA2: only reachable via PTX) ----
__device__ __forceinline__ unsigned long long pack2(float a, float b) {
    unsigned long long r;
    asm("mov.b64 %0, {%1, %2};" : "=l"(r) : "f"(a), "f"(b));
    return r;
}
__device__ __forceinline__ unsigned long long fma2(unsigned long long a,
                                                   unsigned long long b,
                                                   unsigned long long c) {
    unsigned long long d;
    asm("fma.rn.f32x2 %0, %1, %2, %3;" : "=l"(d) : "l"(a), "l"(b), "l"(c));
    return d;
}
__device__ __forceinline__ float2 unpack2(unsigned long long v) {
    float2 f;
    asm("mov.b64 {%0, %1}, %2;" : "=f"(f.x), "=f"(f.y) : "l"(v));
    return f;
}

__global__ void __launch_bounds__(TPB)
nn_min_kernel(const float* __restrict__ centers)
{
    // SoA j-tile (8 KB): LDS.128 per array = pre-packed {j,j+1} f32x2 lanes
    __shared__ __align__(16) float spx[TILE], spy[TILE], spz[TILE], spw[TILE];
    __shared__ float cred[4][IPB];

    const int blk = blockIdx.x;
    const int b   = blk >> 7;          // batch
    const int ib  = (blk & 127) * IPB; // i-range start within batch
    const int tid = threadIdx.x;
    const int l   = tid & 31;          // lane  <-> i
    const int w   = tid >> 5;          // warp  <-> j-quarter

    const float* cb = centers + (size_t)b * NPTS * 3;

    // This lane's i-point (same i for lane l in every warp)
    const int i = ib + l;
    const float xi = cb[3 * i], yi = cb[3 * i + 1], zi = cb[3 * i + 2];
    const unsigned long long ax2 = pack2(-2.0f * xi, -2.0f * xi);
    const unsigned long long ay2 = pack2(-2.0f * yi, -2.0f * yi);
    const unsigned long long az2 = pack2(-2.0f * zi, -2.0f * zi);
    const float sqi = fmaf(xi, xi, fmaf(yi, yi, zi * zi));

    float tA = CUDART_INF_F, tB = CUDART_INF_F;

    // Register double-buffer for staging (4 points/thread)
    float rx[PPT], ry[PPT], rz[PPT];

    // Prologue: load tile 0 into regs, then smem
    #pragma unroll
    for (int k = 0; k < PPT; ++k) {
        const int p = k * TPB + tid;          // tile 0 point index
        rx[k] = cb[3 * p]; ry[k] = cb[3 * p + 1]; rz[k] = cb[3 * p + 2];
    }
    #pragma unroll
    for (int k = 0; k < PPT; ++k) {
        const int p = k * TPB + tid;
        spx[p] = rx[k]; spy[p] = ry[k]; spz[p] = rz[k];
        spw[p] = fmaf(rx[k], rx[k], fmaf(ry[k], ry[k], rz[k] * rz[k]));
    }
    __syncthreads();

    const ulonglong2* px2 = (const ulonglong2*)spx;
    const ulonglong2* py2 = (const ulonglong2*)spy;
    const ulonglong2* pz2 = (const ulonglong2*)spz;
    const ulonglong2* pw2 = (const ulonglong2*)spw;
    const int qbase = w * QPW;                 // this warp's quad range

    for (int t = 0; t < NTILES; ++t) {
        // Prefetch next tile into registers (hidden behind compute)
        if (t + 1 < NTILES) {
            const int base = (t + 1) * TILE;
            #pragma unroll
            for (int k = 0; k < PPT; ++k) {
                const int p = base + k * TPB + tid;
                rx[k] = cb[3 * p]; ry[k] = cb[3 * p + 1]; rz[k] = cb[3 * p + 2];
            }
        }

        // Does this warp's j-quarter contain the block's i-range?
        const bool dg = (t * TILE + w * 128) == (ib & ~127);

        if (!dg) {
            #pragma unroll
            for (int q = 0; q < QPW; ++q) {
                const ulonglong2 px = px2[qbase + q], py = py2[qbase + q];
                const ulonglong2 pz = pz2[qbase + q], pw = pw2[qbase + q];
                unsigned long long t0 = fma2(pz.x, az2, pw.x);
                t0 = fma2(py.x, ay2, t0);
                t0 = fma2(px.x, ax2, t0);
                unsigned long long t1 = fma2(pz.y, az2, pw.y);
                t1 = fma2(py.y, ay2, t1);
                t1 = fma2(px.y, ax2, t1);
                float2 a = unpack2(t0), c = unpack2(t1);
                tA = fminf(tA, fminf(a.x, a.y));
                tB = fminf(tB, fminf(c.x, c.y));
            }
        } else {
            // Exactly one (tile, warp) per block: predicate out j == i
            const int mi = i - t * TILE;       // in [w*128, w*128+128)
            #pragma unroll
            for (int q = 0; q < QPW; ++q) {
                const int jq = w * 128 + q * 4;
                const ulonglong2 px = px2[qbase + q], py = py2[qbase + q];
                const ulonglong2 pz = pz2[qbase + q], pw = pw2[qbase + q];
                unsigned long long t0 = fma2(pz.x, az2, pw.x);
                t0 = fma2(py.x, ay2, t0);
                t0 = fma2(px.x, ax2, t0);
                unsigned long long t1 = fma2(pz.y, az2, pw.y);
                t1 = fma2(py.y, ay2, t1);
                t1 = fma2(px.y, ax2, t1);
                float2 a = unpack2(t0), c = unpack2(t1);
                a.x = (jq + 0 == mi) ? CUDART_INF_F : a.x;
                a.y = (jq + 1 == mi) ? CUDART_INF_F : a.y;
                c.x = (jq + 2 == mi) ? CUDART_INF_F : c.x;
                c.y = (jq + 3 == mi) ? CUDART_INF_F : c.y;
                tA = fminf(tA, fminf(a.x, a.y));
                tB = fminf(tB, fminf(c.x, c.y));
            }
        }
        __syncthreads();

        // Commit prefetched tile to smem
        if (t + 1 < NTILES) {
            #pragma unroll
            for (int k = 0; k < PPT; ++k) {
                const int p = k * TPB + tid;
                spx[p] = rx[k]; spy[p] = ry[k]; spz[p] = rz[k];
                spw[p] = fmaf(rx[k], rx[k], fmaf(ry[k], ry[k], rz[k] * rz[k]));
            }
            __syncthreads();
        }
    }

    // Cross-warp min per i: 4-entry smem combine (no global traffic)
    cred[w][l] = fminf(tA, tB);
    __syncthreads();
    if (w == 0) {
        float m = fminf(fminf(cred[0][l], cred[1][l]),
                        fminf(cred[2][l], cred[3][l]));
        float d2   = fmaxf(sqi + m, 0.0f);            // clamp like reference
        float diff = sqrtf(d2) - TARGET_F;
        float v    = diff * diff;
        #pragma unroll
        for (int o = 16; o > 0; o >>= 1)
            v += __shfl_down_sync(0xffffffffu, v, o);
        if (l == 0) g_partials[blk] = v;              // plain STG
    }
}

__global__ void __launch_bounds__(FIN_TPB)
nn_final_kernel(float* __restrict__ out)
{
    __shared__ float red[FIN_TPB];
    const int tid = threadIdx.x;
    float acc = 0.0f;
    #pragma unroll
    for (int k = 0; k < NBLK / FIN_TPB; ++k)
        acc += g_partials[k * FIN_TPB + tid];
    red[tid] = acc;
    __syncthreads();
    #pragma unroll
    for (int st = FIN_TPB / 2; st > 0; st >>= 1) {
        if (tid < st) red[tid] += red[tid + st];
        __syncthreads();
    }
    if (tid == 0) out[0] = red[0] * (1.0f / (float)TOTPTS);
}

extern "C" void kernel_launch(void* const* d_in, const int* in_sizes, int n_in,
                              void* d_out, int out_size)
{
    const float* centers = (const float*)d_in[0];
    float* out = (float*)d_out;

    nn_min_kernel<<<NBLK, TPB>>>(centers);
    nn_final_kernel<<<1, FIN_TPB>>>(out);
}

// round 14
// speedup vs baseline: 3.1490x; 1.7556x over previous
#include <cuda_runtime.h>
#include <math_constants.h>

// Problem constants (fixed: centers [8, 4096, 3] fp32)
#define BATCH    8
#define NPTS     4096
#define TOTPTS   (BATCH * NPTS)       // 32768
#define TPB      128                  // threads per block (min kernel)
#define IPT      4                    // i-points per thread
#define ITILE    (TPB * IPT)          // 512 i per block
#define NITILES  (NPTS / ITILE)       // 8
#define SSPLIT   64                   // j-splits
#define JT       (NPTS / SSPLIT)      // 64 j per block
#define NBLK_MIN (BATCH * NITILES * SSPLIT)   // 4096
#define CMB_BLKS 128
#define CMB_TPB  128
#define TARGET_F 0.2f

// Scratch (static device globals — no allocation allowed).
// Partial mins in [split][point] layout: coalesced store AND float4 load. 8 MB.
// Fully overwritten every call -> no reset needed.
__device__ float g_pmin[SSPLIT * TOTPTS];
__device__ float g_partials[CMB_BLKS];
__device__ unsigned int g_sync;   // zero-init; self-resets each call

// ---- packed f32x2 helpers (FFMA2: only reachable via PTX) ----
__device__ __forceinline__ unsigned long long pack2(float a, float b) {
    unsigned long long r;
    asm("mov.b64 %0, {%1, %2};" : "=l"(r) : "f"(a), "f"(b));
    return r;
}
__device__ __forceinline__ unsigned long long fma2(unsigned long long a,
                                                   unsigned long long b,
                                                   unsigned long long c) {
    unsigned long long d;
    asm("fma.rn.f32x2 %0, %1, %2, %3;" : "=l"(d) : "l"(a), "l"(b), "l"(c));
    return d;
}
__device__ __forceinline__ float2 unpack2(unsigned long long v) {
    float2 f;
    asm("mov.b64 {%0, %1}, %2;" : "=f"(f.x), "=f"(f.y) : "l"(v));
    return f;
}

__global__ void __launch_bounds__(TPB)
nn_min_kernel(const float* __restrict__ centers)
{
    // SoA j-tile: LDS.128 per array yields pre-packed {j,j+1} f32x2 lanes
    __shared__ __align__(16) float spx[JT], spy[JT], spz[JT], spw[JT];

    const int blk = blockIdx.x;
    const int s   = blk & (SSPLIT - 1);            // j-split
    const int it  = (blk >> 6) & (NITILES - 1);    // i-tile
    const int b   = blk >> 9;                      // batch
    const int tid = threadIdx.x;

    const float* cb = centers + (size_t)b * NPTS * 3;
    const int j_lo  = s  * JT;
    const int i_lo  = it * ITILE;

    // Stage j-tile (64 points)
    for (int p = tid; p < JT; p += TPB) {
        float x = cb[3 * (j_lo + p) + 0];
        float y = cb[3 * (j_lo + p) + 1];
        float z = cb[3 * (j_lo + p) + 2];
        spx[p] = x; spy[p] = y; spz[p] = z;
        spw[p] = fmaf(x, x, fmaf(y, y, z * z));
    }

    // i-constants, pre-packed {c,c} once
    unsigned long long ax2[IPT], ay2[IPT], az2[IPT];
    float sqi[IPT], tminA[IPT], tminB[IPT];
    int   msel[IPT];   // local j index equal to this i (may be out of range)
    #pragma unroll
    for (int k = 0; k < IPT; ++k) {
        const int gi = i_lo + tid + k * TPB;
        float x = cb[3 * gi + 0];
        float y = cb[3 * gi + 1];
        float z = cb[3 * gi + 2];
        ax2[k] = pack2(-2.0f * x, -2.0f * x);
        ay2[k] = pack2(-2.0f * y, -2.0f * y);
        az2[k] = pack2(-2.0f * z, -2.0f * z);
        sqi[k] = fmaf(x, x, fmaf(y, y, z * z));
        tminA[k] = CUDART_INF_F;
        tminB[k] = CUDART_INF_F;
        msel[k] = gi - j_lo;
    }
    __syncthreads();

    const ulonglong2* px2 = (const ulonglong2*)spx;
    const ulonglong2* py2 = (const ulonglong2*)spy;
    const ulonglong2* pz2 = (const ulonglong2*)spz;
    const ulonglong2* pw2 = (const ulonglong2*)spw;

    if ((s >> 3) != it) {
        // Off-diagonal block: clean fully-unrolled loop, no compares
        #pragma unroll
        for (int q = 0; q < JT / 4; ++q) {
            const ulonglong2 px = px2[q], py = py2[q], pz = pz2[q], pw = pw2[q];
            #pragma unroll
            for (int k = 0; k < IPT; ++k) {
                unsigned long long t0 = fma2(pz.x, az2[k], pw.x);
                t0 = fma2(py.x, ay2[k], t0);
                t0 = fma2(px.x, ax2[k], t0);
                unsigned long long t1 = fma2(pz.y, az2[k], pw.y);
                t1 = fma2(py.y, ay2[k], t1);
                t1 = fma2(px.y, ax2[k], t1);
                float2 a = unpack2(t0), c = unpack2(t1);
                tminA[k] = fminf(tminA[k], fminf(a.x, a.y));
                tminB[k] = fminf(tminB[k], fminf(c.x, c.y));
            }
        }
    } else {
        // Diagonal block (1/8 of blocks): predicate out j == i
        #pragma unroll
        for (int q = 0; q < JT / 4; ++q) {
            const int jb = q * 4;
            const ulonglong2 px = px2[q], py = py2[q], pz = pz2[q], pw = pw2[q];
            #pragma unroll
            for (int k = 0; k < IPT; ++k) {
                unsigned long long t0 = fma2(pz.x, az2[k], pw.x);
                t0 = fma2(py.x, ay2[k], t0);
                t0 = fma2(px.x, ax2[k], t0);
                unsigned long long t1 = fma2(pz.y, az2[k], pw.y);
                t1 = fma2(py.y, ay2[k], t1);
                t1 = fma2(px.y, ax2[k], t1);
                float2 a = unpack2(t0), c = unpack2(t1);
                const int m = msel[k];
                a.x = (jb + 0 == m) ? CUDART_INF_F : a.x;
                a.y = (jb + 1 == m) ? CUDART_INF_F : a.y;
                c.x = (jb + 2 == m) ? CUDART_INF_F : c.x;
                c.y = (jb + 3 == m) ? CUDART_INF_F : c.y;
                tminA[k] = fminf(tminA[k], fminf(a.x, a.y));
                tminB[k] = fminf(tminB[k], fminf(c.x, c.y));
            }
        }
    }

    // Coalesced partial store: pm[s][point]  (plain STG, no atomics)
    float* pm = g_pmin + (size_t)s * TOTPTS + b * NPTS + i_lo + tid;
    #pragma unroll
    for (int k = 0; k < IPT; ++k)
        pm[k * TPB] = sqi[k] + fminf(tminA[k], tminB[k]);
}

// Fused combine+final. 16384 threads: thread covers 4 points (one float4
// group pg = gid>>1) over half the splits (32 independent LDG.128, MLP=32).
// Pair-combine halves in smem, per-point loss, block reduce, last-block-done
// final sum in fixed order (deterministic).
__global__ void __launch_bounds__(CMB_TPB)
nn_combine_final(float* __restrict__ out)
{
    __shared__ float4 sm4[CMB_TPB];
    __shared__ float  red[CMB_TPB / 2];
    const int tid = threadIdx.x;
    const int gid = blockIdx.x * CMB_TPB + tid;
    const int pg  = gid >> 1;                 // float4 point-group 0..8191
    const int s0  = (gid & 1) * (SSPLIT / 2); // this thread's split half

    const float4* pm4 = (const float4*)g_pmin;
    float4 m = make_float4(CUDART_INF_F, CUDART_INF_F, CUDART_INF_F, CUDART_INF_F);
    #pragma unroll
    for (int k = 0; k < SSPLIT / 2; ++k) {
        const float4 v = pm4[(size_t)(s0 + k) * (TOTPTS / 4) + pg];
        m.x = fminf(m.x, v.x);
        m.y = fminf(m.y, v.y);
        m.z = fminf(m.z, v.z);
        m.w = fminf(m.w, v.w);
    }
    sm4[tid] = m;
    __syncthreads();

    if ((tid & 1) == 0) {
        const float4 a = sm4[tid], c = sm4[tid + 1];
        float dx = sqrtf(fmaxf(fminf(a.x, c.x), 0.0f)) - TARGET_F;
        float dy = sqrtf(fmaxf(fminf(a.y, c.y), 0.0f)) - TARGET_F;
        float dz = sqrtf(fmaxf(fminf(a.z, c.z), 0.0f)) - TARGET_F;
        float dw = sqrtf(fmaxf(fminf(a.w, c.w), 0.0f)) - TARGET_F;
        red[tid >> 1] = (dx * dx + dy * dy) + (dz * dz + dw * dw);
    }
    __syncthreads();
    #pragma unroll
    for (int st = CMB_TPB / 4; st > 0; st >>= 1) {
        if (tid < st) red[tid] += red[tid + st];
        __syncthreads();
    }
    if (tid == 0) {
        g_partials[blockIdx.x] = red[0];
        __threadfence();
        if (atomicAdd(&g_sync, 1u) == CMB_BLKS - 1) {
            __threadfence();
            float sum = 0.0f;
            for (int i = 0; i < CMB_BLKS; ++i) sum += g_partials[i];
            out[0] = sum * (1.0f / (float)TOTPTS);
            g_sync = 0;   // reset for next replay
        }
    }
}

extern "C" void kernel_launch(void* const* d_in, const int* in_sizes, int n_in,
                              void* d_out, int out_size)
{
    const float* centers = (const float*)d_in[0];
    float* out = (float*)d_out;

    nn_min_kernel<<<NBLK_MIN, TPB>>>(centers);
    nn_combine_final<<<CMB_BLKS, CMB_TPB>>>(out);
}

// round 15
// speedup vs baseline: 3.3723x; 1.0709x over previous
#include <cuda_runtime.h>
#include <math_constants.h>

// Problem constants (fixed: centers [8, 4096, 3] fp32)
#define BATCH    8
#define NPTS     4096
#define TOTPTS   (BATCH * NPTS)       // 32768
#define TPB      128                  // threads per block (min kernel)
#define IPT      4                    // i-points per thread
#define ITILE    (TPB * IPT)          // 512 i per block
#define NITILES  (NPTS / ITILE)       // 8
#define SSPLIT   64                   // j-splits
#define JT       (NPTS / SSPLIT)      // 64 j per block
#define NBLK_MIN (BATCH * NITILES * SSPLIT)   // 4096
#define NPG      (TOTPTS / 4)         // 8192 float4 point-groups
#define CMB_BLKS 512
#define CMB_TPB  128
#define PG_PER_BLK 16                 // point-groups per combine block
#define TARGET_F 0.2f

// Scratch (static device globals — no allocation allowed).
// Partial mins in [split][point] layout: coalesced store AND float4 load. 8 MB.
// Fully overwritten every call -> no reset needed.
__device__ float g_pmin[SSPLIT * TOTPTS];
__device__ float g_partials[CMB_BLKS];
__device__ unsigned int g_sync;   // zero-init; self-resets each call

// ---- packed f32x2 helpers (FFMA2: only reachable via PTX) ----
__device__ __forceinline__ unsigned long long pack2(float a, float b) {
    unsigned long long r;
    asm("mov.b64 %0, {%1, %2};" : "=l"(r) : "f"(a), "f"(b));
    return r;
}
__device__ __forceinline__ unsigned long long fma2(unsigned long long a,
                                                   unsigned long long b,
                                                   unsigned long long c) {
    unsigned long long d;
    asm("fma.rn.f32x2 %0, %1, %2, %3;" : "=l"(d) : "l"(a), "l"(b), "l"(c));
    return d;
}
__device__ __forceinline__ float2 unpack2(unsigned long long v) {
    float2 f;
    asm("mov.b64 {%0, %1}, %2;" : "=f"(f.x), "=f"(f.y) : "l"(v));
    return f;
}
__device__ __forceinline__ float4 fmin4(float4 a, float4 b) {
    return make_float4(fminf(a.x, b.x), fminf(a.y, b.y),
                       fminf(a.z, b.z), fminf(a.w, b.w));
}

__global__ void __launch_bounds__(TPB)
nn_min_kernel(const float* __restrict__ centers)
{
    // SoA j-tile: LDS.128 per array yields pre-packed {j,j+1} f32x2 lanes
    __shared__ __align__(16) float spx[JT], spy[JT], spz[JT], spw[JT];

    const int blk = blockIdx.x;
    const int s   = blk & (SSPLIT - 1);            // j-split
    const int it  = (blk >> 6) & (NITILES - 1);    // i-tile
    const int b   = blk >> 9;                      // batch
    const int tid = threadIdx.x;

    const float* cb = centers + (size_t)b * NPTS * 3;
    const int j_lo  = s  * JT;
    const int i_lo  = it * ITILE;

    // Stage j-tile (64 points)
    for (int p = tid; p < JT; p += TPB) {
        float x = cb[3 * (j_lo + p) + 0];
        float y = cb[3 * (j_lo + p) + 1];
        float z = cb[3 * (j_lo + p) + 2];
        spx[p] = x; spy[p] = y; spz[p] = z;
        spw[p] = fmaf(x, x, fmaf(y, y, z * z));
    }

    // i-constants, pre-packed {c,c} once
    unsigned long long ax2[IPT], ay2[IPT], az2[IPT];
    float sqi[IPT], tminA[IPT], tminB[IPT];
    int   msel[IPT];   // local j index equal to this i (may be out of range)
    #pragma unroll
    for (int k = 0; k < IPT; ++k) {
        const int gi = i_lo + tid + k * TPB;
        float x = cb[3 * gi + 0];
        float y = cb[3 * gi + 1];
        float z = cb[3 * gi + 2];
        ax2[k] = pack2(-2.0f * x, -2.0f * x);
        ay2[k] = pack2(-2.0f * y, -2.0f * y);
        az2[k] = pack2(-2.0f * z, -2.0f * z);
        sqi[k] = fmaf(x, x, fmaf(y, y, z * z));
        tminA[k] = CUDART_INF_F;
        tminB[k] = CUDART_INF_F;
        msel[k] = gi - j_lo;
    }
    __syncthreads();

    const ulonglong2* px2 = (const ulonglong2*)spx;
    const ulonglong2* py2 = (const ulonglong2*)spy;
    const ulonglong2* pz2 = (const ulonglong2*)spz;
    const ulonglong2* pw2 = (const ulonglong2*)spw;

    if ((s >> 3) != it) {
        // Off-diagonal block: clean fully-unrolled loop, no compares
        #pragma unroll
        for (int q = 0; q < JT / 4; ++q) {
            const ulonglong2 px = px2[q], py = py2[q], pz = pz2[q], pw = pw2[q];
            #pragma unroll
            for (int k = 0; k < IPT; ++k) {
                unsigned long long t0 = fma2(pz.x, az2[k], pw.x);
                t0 = fma2(py.x, ay2[k], t0);
                t0 = fma2(px.x, ax2[k], t0);
                unsigned long long t1 = fma2(pz.y, az2[k], pw.y);
                t1 = fma2(py.y, ay2[k], t1);
                t1 = fma2(px.y, ax2[k], t1);
                float2 a = unpack2(t0), c = unpack2(t1);
                tminA[k] = fminf(tminA[k], fminf(a.x, a.y));
                tminB[k] = fminf(tminB[k], fminf(c.x, c.y));
            }
        }
    } else {
        // Diagonal block (1/8 of blocks): predicate out j == i
        #pragma unroll
        for (int q = 0; q < JT / 4; ++q) {
            const int jb = q * 4;
            const ulonglong2 px = px2[q], py = py2[q], pz = pz2[q], pw = pw2[q];
            #pragma unroll
            for (int k = 0; k < IPT; ++k) {
                unsigned long long t0 = fma2(pz.x, az2[k], pw.x);
                t0 = fma2(py.x, ay2[k], t0);
                t0 = fma2(px.x, ax2[k], t0);
                unsigned long long t1 = fma2(pz.y, az2[k], pw.y);
                t1 = fma2(py.y, ay2[k], t1);
                t1 = fma2(px.y, ax2[k], t1);
                float2 a = unpack2(t0), c = unpack2(t1);
                const int m = msel[k];
                a.x = (jb + 0 == m) ? CUDART_INF_F : a.x;
                a.y = (jb + 1 == m) ? CUDART_INF_F : a.y;
                c.x = (jb + 2 == m) ? CUDART_INF_F : c.x;
                c.y = (jb + 3 == m) ? CUDART_INF_F : c.y;
                tminA[k] = fminf(tminA[k], fminf(a.x, a.y));
                tminB[k] = fminf(tminB[k], fminf(c.x, c.y));
            }
        }
    }

    // Coalesced partial store: pm[s][point]  (plain STG, no atomics)
    float* pm = g_pmin + (size_t)s * TOTPTS + b * NPTS + i_lo + tid;
    #pragma unroll
    for (int k = 0; k < IPT; ++k)
        pm[k * TPB] = sqi[k] + fminf(tminA[k], tminB[k]);
}

// Fused combine+final, MLP-by-construction.
// 512 blocks x 128 threads; thread = (point-group pidx, split-octet oct).
// 8 independent LDG.128 batch-loaded into separate registers, then tree-min.
// Cross-octet combine in smem (same block), loss per point, half-warp reduce,
// last-block-done final (fixed-order, deterministic).
__global__ void __launch_bounds__(CMB_TPB)
nn_combine_final(float* __restrict__ out)
{
    __shared__ float4 sm[8][PG_PER_BLK];
    __shared__ float  red[PG_PER_BLK];
    __shared__ bool   is_last;

    const int tid  = threadIdx.x;
    const int pidx = tid & (PG_PER_BLK - 1);       // 0..15
    const int oct  = tid >> 4;                     // 0..7
    const int pg   = blockIdx.x * PG_PER_BLK + pidx;

    const float4* pm4 = (const float4*)g_pmin;
    const size_t base = (size_t)(oct * 8) * NPG + pg;

    // 8 independent loads into separate registers (forced MLP=8)
    const float4 v0 = pm4[base + 0 * NPG];
    const float4 v1 = pm4[base + 1 * NPG];
    const float4 v2 = pm4[base + 2 * NPG];
    const float4 v3 = pm4[base + 3 * NPG];
    const float4 v4 = pm4[base + 4 * NPG];
    const float4 v5 = pm4[base + 5 * NPG];
    const float4 v6 = pm4[base + 6 * NPG];
    const float4 v7 = pm4[base + 7 * NPG];
    sm[oct][pidx] = fmin4(fmin4(fmin4(v0, v1), fmin4(v2, v3)),
                          fmin4(fmin4(v4, v5), fmin4(v6, v7)));
    __syncthreads();

    if (tid < PG_PER_BLK) {
        float4 m = fmin4(fmin4(fmin4(sm[0][tid], sm[1][tid]),
                               fmin4(sm[2][tid], sm[3][tid])),
                         fmin4(fmin4(sm[4][tid], sm[5][tid]),
                               fmin4(sm[6][tid], sm[7][tid])));
        float dx = sqrtf(fmaxf(m.x, 0.0f)) - TARGET_F;
        float dy = sqrtf(fmaxf(m.y, 0.0f)) - TARGET_F;
        float dz = sqrtf(fmaxf(m.z, 0.0f)) - TARGET_F;
        float dw = sqrtf(fmaxf(m.w, 0.0f)) - TARGET_F;
        red[tid] = (dx * dx + dy * dy) + (dz * dz + dw * dw);
    }
    __syncthreads();
    if (tid == 0) {
        float v = 0.0f;
        #pragma unroll
        for (int p = 0; p < PG_PER_BLK; ++p) v += red[p];
        g_partials[blockIdx.x] = v;
        __threadfence();
        is_last = (atomicAdd(&g_sync, 1u) == CMB_BLKS - 1);
    }
    __syncthreads();
    if (!is_last) return;
    __threadfence();

    // Last block: fixed-order deterministic sum of 512 partials
    float acc = g_partials[tid]
              + g_partials[tid + 128]
              + g_partials[tid + 256]
              + g_partials[tid + 384];
    __shared__ float fin[CMB_TPB];
    fin[tid] = acc;
    __syncthreads();
    #pragma unroll
    for (int st = CMB_TPB / 2; st > 0; st >>= 1) {
        if (tid < st) fin[tid] += fin[tid + st];
        __syncthreads();
    }
    if (tid == 0) {
        out[0] = fin[0] * (1.0f / (float)TOTPTS);
        g_sync = 0;   // reset for next replay
    }
}

extern "C" void kernel_launch(void* const* d_in, const int* in_sizes, int n_in,
                              void* d_out, int out_size)
{
    const float* centers = (const float*)d_in[0];
    float* out = (float*)d_out;

    nn_min_kernel<<<NBLK_MIN, TPB>>>(centers);
    nn_combine_final<<<CMB_BLKS, CMB_TPB>>>(out);
}